// round 1
// baseline (speedup 1.0000x reference)
#include <cuda_runtime.h>

#define MAXDISP 48
#define DISP 49          // MAXDISP + 1
#define GROUP 8
#define CPG 8            // channels per group (64 / 8)
#define HH 96
#define WW 320
#define BB 2
#define EPSN 1e-5f

// One CTA per (b, g, h) row. 320 threads, thread t <-> column w = t.
// Each thread: load 8-ch x and y vectors (coalesced across t per channel),
// normalize in registers, stash yn in smem with 48B row stride
// (conflict-free float4 pair loads), then sweep all 49 disparities.
__global__ __launch_bounds__(WW, 4)
void cost_volume_kernel(const float* __restrict__ x,
                        const float* __restrict__ y,
                        float* __restrict__ out) {
    __shared__ __align__(16) float yn[WW][12];  // [w][8 ch + 4 pad] -> 48B stride

    const int t = threadIdx.x;        // w position
    const int h = blockIdx.x;
    const int g = blockIdx.y;
    const int b = blockIdx.z;

    // x/y layout: [b, c=64, h, w]; group g owns channels g*8 .. g*8+7
    const int chw = HH * WW;
    const int in_base = ((b * 64 + g * CPG) * HH + h) * WW + t;

    float xv[CPG];
    float yv[CPG];
    float sx = 0.f, sy = 0.f;
#pragma unroll
    for (int c = 0; c < CPG; c++) {
        xv[c] = x[in_base + c * chw];
        yv[c] = y[in_base + c * chw];
        sx += xv[c] * xv[c];
        sy += yv[c] * yv[c];
    }
    const float ix = 1.f / (sqrtf(sx) + EPSN);
    const float iy = 1.f / (sqrtf(sy) + EPSN);

#pragma unroll
    for (int c = 0; c < CPG; c++) {
        xv[c] *= ix;
        yn[t][c] = yv[c] * iy;
    }
    __syncthreads();

    // out layout: [b, g, d, h, w]; d stride = HH*WW
    float* outp = out + ((b * GROUP + g) * DISP * HH + h) * WW + t;

    // cost for the zero-padded region (w < d): sum |xn_c - 0|
    float s_pad = 0.f;
#pragma unroll
    for (int c = 0; c < CPG; c++) s_pad += fabsf(xv[c]);

    for (int d = 0; d < DISP; d++) {
        float s;
        if (t >= d) {
            const float4 a  = *(const float4*)&yn[t - d][0];
            const float4 bb = *(const float4*)&yn[t - d][4];
            s = fabsf(xv[0] - a.x)  + fabsf(xv[1] - a.y)
              + fabsf(xv[2] - a.z)  + fabsf(xv[3] - a.w)
              + fabsf(xv[4] - bb.x) + fabsf(xv[5] - bb.y)
              + fabsf(xv[6] - bb.z) + fabsf(xv[7] - bb.w);
        } else {
            s = s_pad;
        }
        outp[d * chw] = s;
    }
}

extern "C" void kernel_launch(void* const* d_in, const int* in_sizes, int n_in,
                              void* d_out, int out_size) {
    const float* x = (const float*)d_in[0];
    const float* y = (const float*)d_in[1];
    float* out = (float*)d_out;

    dim3 grid(HH, GROUP, BB);   // 96 x 8 x 2 = 1536 CTAs
    dim3 block(WW);             // 320 threads
    cost_volume_kernel<<<grid, block>>>(x, y, out);
}